// round 16
// baseline (speedup 1.0000x reference)
#include <cuda_runtime.h>
#include <cuda_fp16.h>

// ============================================================================
// LSTMDecoder: 2-layer LSTM (H=1024, B=2, T=1023) + CE loss.
// R16 (= R9..R15 resubmit; every attempt since R8 hit GPUAcquisitionTimeout
// and never executed. Static audit this round re-verified occupancy,
// graph-replay determinism, and cross-SM memory ordering; queued refinements
// remain invalidated by analysis, so this is still the best-theory kernel):
//   weights held in SMEM as fp16 (192KB/block), fp32 accumulation.
//   Distributed flag grid barrier. Wavefront: phase k does L0[k] || L1[k-1]
//   || logits[k-2] || nll[k-3].
// ============================================================================

#define NBLK        148
#define LSTM_BLOCKS 128
#define HDIM        1024
#define NCLS        30
#define NB          2
#define SEQ         1024
#define NT          1023
#define NPHASE      1026

// dynamic smem layout (bytes)
#define SMW_BYTES   (8 * 12 * 1024 * 2)   // 196608: 8 warps x 12 rows x 1024 half
#define SMH0_OFF    SMW_BYTES
#define SMH1_OFF    (SMW_BYTES + 8192)
#define SMEM_BYTES  (SMW_BYTES + 16384)   // 212992

__device__ float g_base[NB][4096];
__device__ float g_table[NCLS][4096];
__device__ float g_bias1[4096];
__device__ float g_h0[2][NB][HDIM];
__device__ float g_h1[2][NB][HDIM];
__device__ float g_logits[2][NB][NCLS];
__device__ int   g_ids[NB][SEQ];
__device__ float g_masksum;
__device__ unsigned g_arrive[NBLK];

__device__ __forceinline__ float sigm(float x)   { return 1.0f / (1.0f + __expf(-x)); }
__device__ __forceinline__ float tanh_f(float x) { return 1.0f - 2.0f / (1.0f + __expf(2.0f * x)); }

#define WRED(v) { \
  v += __shfl_xor_sync(0xffffffffu, (v), 16); \
  v += __shfl_xor_sync(0xffffffffu, (v), 8);  \
  v += __shfl_xor_sync(0xffffffffu, (v), 4);  \
  v += __shfl_xor_sync(0xffffffffu, (v), 2);  \
  v += __shfl_xor_sync(0xffffffffu, (v), 1);  \
}

#define DOT4F(acc, w4, h4) \
  acc = fmaf((w4).x,(h4).x, fmaf((w4).y,(h4).y, fmaf((w4).z,(h4).z, fmaf((w4).w,(h4).w,(acc)))));

// 4 fp16 weights vs two fp32 h-vectors (batch0/batch1), fp32 accumulation
__device__ __forceinline__ void dot4h(const __half* w, const float4 hA, const float4 hB,
                                      float& accA, float& accB) {
  const uint2 raw = *(const uint2*)w;
  const __half2 p0 = *(const __half2*)&raw.x;
  const __half2 p1 = *(const __half2*)&raw.y;
  const float w0 = __low2float(p0), w1 = __high2float(p0);
  const float w2 = __low2float(p1), w3 = __high2float(p1);
  accA = fmaf(w0,hA.x, fmaf(w1,hA.y, fmaf(w2,hA.z, fmaf(w3,hA.w, accA))));
  accB = fmaf(w0,hB.x, fmaf(w1,hB.y, fmaf(w2,hB.z, fmaf(w3,hB.w, accB))));
}

// Distributed grid barrier: fence (all threads, covers every writer), arrive
// flag store, 148 parallel pollers. Flags are monotonic (reset by init_kernel
// each replay).
__device__ __forceinline__ void grid_barrier(unsigned p1) {
  __threadfence();
  __syncthreads();
  volatile unsigned* fl = (volatile unsigned*)g_arrive;
  if (threadIdx.x == 0) fl[blockIdx.x] = p1;
  if (threadIdx.x < NBLK) { while (fl[threadIdx.x] < p1) { } }
  __syncthreads();
}

// ---------------------------------------------------------------------------
__global__ __launch_bounds__(256) void init_kernel(const int* __restrict__ ids_raw,
                                                   const float* __restrict__ mask) {
  const int tid = threadIdx.x;
  const int gid = blockIdx.x * 256 + tid;   // 8 blocks -> 2048 threads
  float* h0 = (float*)g_h0;
  float* h1 = (float*)g_h1;
  for (int i = gid; i < 2 * NB * HDIM; i += 2048) { h0[i] = 0.0f; h1[i] = 0.0f; }
  if (gid < NBLK) g_arrive[gid] = 0u;

  if (blockIdx.x == 0) {
    // ids dtype auto-detect: int64 ids in [0,30) have all-zero high words.
    __shared__ int s_odd;
    __shared__ float red[256];
    if (tid == 0) s_odd = 0;
    __syncthreads();
    int loc = 0;
    for (int i = tid; i < NB * SEQ; i += 256) if (i & 1) loc |= ids_raw[i];
    if (loc) atomicOr(&s_odd, 1);
    __syncthreads();
    const bool is64 = (s_odd == 0);
    int* idst = (int*)g_ids;
    for (int i = tid; i < NB * SEQ; i += 256)
      idst[i] = is64 ? (int)(((const long long*)ids_raw)[i]) : ids_raw[i];

    float s = 0.0f;
    for (int i = tid; i < NB * (SEQ - 1); i += 256) {
      int b = i / (SEQ - 1), p = i - b * (SEQ - 1);
      s += mask[b * SEQ + 1 + p];
    }
    red[tid] = s;
    __syncthreads();
    for (int off = 128; off > 0; off >>= 1) {
      if (tid < off) red[tid] += red[tid + off];
      __syncthreads();
    }
    if (tid == 0) g_masksum = red[0];
  }
}

// ---------------------------------------------------------------------------
__global__ __launch_bounds__(256) void precompute(
    const float* __restrict__ cond, const float* __restrict__ emb,
    const float* __restrict__ Wih0, const float* __restrict__ bih0,
    const float* __restrict__ bhh0, const float* __restrict__ bih1,
    const float* __restrict__ bhh1) {
  __shared__ float smc[NB * HDIM];
  __shared__ float sme[NCLS * 128];
  const int tid = threadIdx.x, wid = tid >> 5, lane = tid & 31;
  for (int i = tid; i < NB * HDIM; i += 256)  smc[i] = cond[i];
  for (int i = tid; i < NCLS * 128; i += 256) sme[i] = emb[i];
  __syncthreads();

  const int j = (blockIdx.x << 3) + wid;             // 512 blocks * 8 warps
  const float* w = Wih0 + (size_t)j * 1152;

  float a0 = 0.0f, a1 = 0.0f;
  #pragma unroll
  for (int ch = 0; ch < 8; ch++) {
    const int idx = (ch << 7) + (lane << 2);
    const float4 w4 = *(const float4*)&w[idx];
    const float4 ca = *(const float4*)&smc[idx];
    const float4 cb = *(const float4*)&smc[HDIM + idx];
    DOT4F(a0, w4, ca);
    DOT4F(a1, w4, cb);
  }
  WRED(a0); WRED(a1);

  const float4 wt = *(const float4*)&w[HDIM + (lane << 2)];
  for (int c = 0; c < NCLS; c++) {
    const float4 e = *(const float4*)&sme[(c << 7) + (lane << 2)];
    float t = 0.0f;
    DOT4F(t, wt, e);
    WRED(t);
    if (lane == 0) g_table[c][j] = t;
  }
  if (lane == 0) {
    const float bb = bih0[j] + bhh0[j];
    g_base[0][j] = a0 + bb;
    g_base[1][j] = a1 + bb;
    g_bias1[j]   = bih1[j] + bhh1[j];
  }
}

// ---------------------------------------------------------------------------
__global__ __launch_bounds__(256, 1) void lstm_persist(
    const float* __restrict__ Whh0, const float* __restrict__ Wih1,
    const float* __restrict__ Whh1, const float* __restrict__ fcw,
    const float* __restrict__ fcb,  float* __restrict__ out) {
  extern __shared__ char smem[];
  __half* smW  = (__half*)smem;                 // [8 warps][12 rows][1024]
  float*  smH0 = (float*)(smem + SMH0_OFF);     // h0[k-1], [NB][HDIM]
  float*  smH1 = (float*)(smem + SMH1_OFF);     // h1[k-2], [NB][HDIM]

  const int tid = threadIdx.x, bid = blockIdx.x;
  const int wid = tid >> 5, lane = tid & 31;
  const bool lstm = (bid < LSTM_BLOCKS);
  const int u  = (bid << 3) + wid;
  const int lw = ((bid - LSTM_BLOCKS) << 3) + wid;

  __half* wp = smW + wid * 12288;               // this warp's 12 rows

  // ---- prologue: convert this warp's 12 weight rows fp32 -> fp16 in smem ----
  if (lstm) {
    const float* rp[12] = {
      Whh0 + (size_t)(u)        * HDIM, Whh0 + (size_t)(1024 + u) * HDIM,
      Whh0 + (size_t)(2048 + u) * HDIM, Whh0 + (size_t)(3072 + u) * HDIM,
      Wih1 + (size_t)(u)        * HDIM, Wih1 + (size_t)(1024 + u) * HDIM,
      Wih1 + (size_t)(2048 + u) * HDIM, Wih1 + (size_t)(3072 + u) * HDIM,
      Whh1 + (size_t)(u)        * HDIM, Whh1 + (size_t)(1024 + u) * HDIM,
      Whh1 + (size_t)(2048 + u) * HDIM, Whh1 + (size_t)(3072 + u) * HDIM };
    #pragma unroll
    for (int r = 0; r < 12; r++) {
      const float* src = rp[r];
      __half* dst = wp + r * 1024;
      for (int i = lane * 4; i < 1024; i += 128) {
        const float4 v = *(const float4*)&src[i];
        *(__half2*)&dst[i]     = __floats2half2_rn(v.x, v.y);
        *(__half2*)&dst[i + 2] = __floats2half2_rn(v.z, v.w);
      }
    }
  }

  float c0reg = 0.0f, c1reg = 0.0f;   // lane0: batch0, lane1: batch1
  float nll_acc = 0.0f;

  for (int k = 0; k < NPHASE; k++) {
    const int pc = k & 1, pp = pc ^ 1;

    // snapshot cross-block state from L2 (L1 is not coherent across SMs)
    if (lstm) {
      const float4* s0 = (const float4*)&g_h0[pp][0][0];
      const float4* s1 = (const float4*)&g_h1[pc][0][0];
      ((float4*)smH0)[tid]       = __ldcg(s0 + tid);
      ((float4*)smH0)[tid + 256] = __ldcg(s0 + tid + 256);
      ((float4*)smH1)[tid]       = __ldcg(s1 + tid);
      ((float4*)smH1)[tid + 256] = __ldcg(s1 + tid + 256);
    } else {
      const float4* s1 = (const float4*)&g_h1[pc][0][0];
      ((float4*)smH1)[tid]       = __ldcg(s1 + tid);
      ((float4*)smH1)[tid + 256] = __ldcg(s1 + tid + 256);
    }
    __syncthreads();

    if (lstm) {
      // 16 accumulators: a[0..7] = L0 {i,f,g,o}x{b0,b1}; a[8..15] = L1
      float a[16];
      #pragma unroll
      for (int i = 0; i < 16; i++) a[i] = 0.0f;

      // fused: L0 gates + L1 input-gates, both consume h0[k-1]
      #pragma unroll
      for (int ch = 0; ch < 8; ch++) {
        const int off = (ch << 7) + (lane << 2);
        const float4 hA = *(const float4*)&smH0[off];
        const float4 hB = *(const float4*)&smH0[HDIM + off];
        #pragma unroll
        for (int r = 0; r < 8; r++)
          dot4h(wp + (r << 10) + off, hA, hB, a[2*r], a[2*r + 1]);
      }
      // L1 recurrent gates consume h1[k-2]
      #pragma unroll
      for (int ch = 0; ch < 8; ch++) {
        const int off = (ch << 7) + (lane << 2);
        const float4 hC = *(const float4*)&smH1[off];
        const float4 hD = *(const float4*)&smH1[HDIM + off];
        #pragma unroll
        for (int r = 0; r < 4; r++)
          dot4h(wp + ((8 + r) << 10) + off, hC, hD, a[8 + 2*r], a[9 + 2*r]);
      }
      #pragma unroll
      for (int i = 0; i < 16; i++) WRED(a[i]);

      if (lane < 2) {
        // ---- Layer 0 epilogue, time k ----
        if (k <= NT - 1) {
          const int id = g_ids[lane][k];
          const float pi = g_base[lane][u]        + g_table[id][u];
          const float pf = g_base[lane][1024 + u] + g_table[id][1024 + u];
          const float pg = g_base[lane][2048 + u] + g_table[id][2048 + u];
          const float po = g_base[lane][3072 + u] + g_table[id][3072 + u];
          const float iv = sigm(  a[0 + lane] + pi);
          const float fv = sigm(  a[2 + lane] + pf);
          const float gv = tanh_f(a[4 + lane] + pg);
          const float ov = sigm(  a[6 + lane] + po);
          c0reg = fv * c0reg + iv * gv;
          __stcg(&g_h0[pc][lane][u], ov * tanh_f(c0reg));
        }
        // ---- Layer 1 epilogue, time k-1 ----
        if (k >= 1 && k <= NT) {
          const float iv = sigm(  a[8  + lane] + g_bias1[u]);
          const float fv = sigm(  a[10 + lane] + g_bias1[1024 + u]);
          const float gv = tanh_f(a[12 + lane] + g_bias1[2048 + u]);
          const float ov = sigm(  a[14 + lane] + g_bias1[3072 + u]);
          c1reg = fv * c1reg + iv * gv;
          __stcg(&g_h1[pp][lane][u], ov * tanh_f(c1reg));
        }
      }
    } else {
      // ---- logits, time k-2 ----
      if (lw < 2 * NCLS && k >= 2 && k <= NT + 1) {
        const int cls = lw >> 1, b = lw & 1;
        const float* w = fcw + (size_t)cls * HDIM;
        float acc = 0.0f;
        #pragma unroll
        for (int ch = 0; ch < 8; ch++) {
          const int off = (ch << 7) + (lane << 2);
          const float4 w4 = *(const float4*)&w[off];
          const float4 h4 = *(const float4*)&smH1[b * HDIM + off];
          DOT4F(acc, w4, h4);
        }
        WRED(acc);
        if (lane == 0) __stcg(&g_logits[pc][b][cls], acc + fcb[cls]);
      }
      // ---- nll, time k-3 ----
      if (bid == NBLK - 1 && wid == 7 && lane < 2 && k >= 3) {
        const int t = k - 3;
        const float* lg = &g_logits[pp][lane][0];
        float mx = -1e30f;
        #pragma unroll
        for (int c = 0; c < NCLS; c++) mx = fmaxf(mx, __ldcg(lg + c));
        float se = 0.0f;
        #pragma unroll
        for (int c = 0; c < NCLS; c++) se += __expf(__ldcg(lg + c) - mx);
        const int tgt = g_ids[lane][t + 1];
        nll_acc += logf(se) + mx - __ldcg(lg + tgt);
      }
    }
    grid_barrier((unsigned)(k + 1));
  }

  if (bid == NBLK - 1 && wid == 7) {
    const float n1 = __shfl_sync(0xffffffffu, nll_acc, 1);
    if (lane == 0) {
      const float tot  = nll_acc + n1;
      const float ce   = tot / (float)(NB * NT);
      const float ms   = g_masksum;
      const float loss = ce + (ce * ms) / ms;   // masked == ce (scalar ce)
      out[0] = loss;
    }
  }
}

// ---------------------------------------------------------------------------
extern "C" void kernel_launch(void* const* d_in, const int* in_sizes, int n_in,
                              void* d_out, int out_size) {
  (void)in_sizes; (void)n_in; (void)out_size;
  const int*   ids  = (const int*)d_in[0];
  const float* mask = (const float*)d_in[1];
  const float* cond = (const float*)d_in[2];
  const float* emb  = (const float*)d_in[3];
  const float* Wih0 = (const float*)d_in[4];
  const float* Whh0 = (const float*)d_in[5];
  const float* bih0 = (const float*)d_in[6];
  const float* bhh0 = (const float*)d_in[7];
  const float* Wih1 = (const float*)d_in[8];
  const float* Whh1 = (const float*)d_in[9];
  const float* bih1 = (const float*)d_in[10];
  const float* bhh1 = (const float*)d_in[11];
  const float* fcw  = (const float*)d_in[12];
  const float* fcb  = (const float*)d_in[13];

  cudaFuncSetAttribute(lstm_persist, cudaFuncAttributeMaxDynamicSharedMemorySize,
                       SMEM_BYTES);

  init_kernel<<<8, 256>>>(ids, mask);
  precompute<<<512, 256>>>(cond, emb, Wih0, bih0, bhh0, bih1, bhh1);
  lstm_persist<<<NBLK, 256, SMEM_BYTES>>>(Whh0, Wih1, Whh1, fcw, fcb, (float*)d_out);
}